// round 14
// baseline (speedup 1.0000x reference)
#include <cuda_runtime.h>

#define NSITE 40
#define NSTEP 20
#define NCTA  144
#define NTHR  512

typedef unsigned long long ull;

__device__ __align__(16) float g_L[2][131072];   // left  env [a][w][b]
__device__ __align__(16) float g_R[2][131072];   // right env [a][x][b]
__device__ __align__(16) float g_N[2][16384];
__device__ __align__(16) float g_Nr[2][16384];
__device__ __align__(16) float g_T1[262144];     // left  T1 [pp][(2w+i)][b*2+pl]
__device__ __align__(16) float g_T1r[262144];    // right T1 same layout
__device__ __align__(16) float g_Tn[32768];      // left  Tn transposed [k][p]
__device__ __align__(16) float g_Tnr[32768];
__device__ __align__(16) float g_mT[655360];     // sites 20..39: [p*256+i*128+a] = m[a,i,p]
__device__ __align__(16) float g_hT[5120];       // sites 20..39: [x*32+w*4+i*2+j]
__device__ float g_parts[NCTA];
__device__ __align__(128) unsigned g_bars[128];  // 4 counters, 128B apart
__device__ __align__(128) unsigned g_fin[32];

// smem (bytes), energy CTA:
//   smM 0(128K)
//   smT2f 131072(20480: [256k][20f] rows, pl*8+x in first 16)
//   smX   151552(16384: phase-A k-split exchange, ull[8][256])
//   smA   167936(16K) | smT1 185344(16K, ends 201728)
//   smH   201728(1K)  — DEAD TAIL region: never aliased, safe for in-flight prefetch
//   smPE0 @167936(32K = 167936..200704, aliases A/T1 — both guarded by syncs)
//   smPE1 @131072(32K, aliases T2f+X — dead after main loop, guarded by sync)
// norm CTA: smM 0(128K) | smTn 131072(32K) | smAn 163840(16K) | smPN 180224(32K)
#define SMEM_BYTES 212992
#define OFF_M    0
#define OFF_T2F  131072
#define OFF_X    151552
#define OFF_A    167936
#define OFF_T1S  185344
#define OFF_H    201728
#define OFF_PE0  167936
#define OFF_PE1  131072
#define OFF_TN   131072
#define OFF_AN   163840
#define OFF_PN   180224
#define OFF_XN   180224

__device__ __forceinline__ void cp16(void* s, const void* g) {
    unsigned sa = (unsigned)__cvta_generic_to_shared(s);
    asm volatile("cp.async.cg.shared.global [%0], [%1], 16;" :: "r"(sa), "l"(g));
}
__device__ __forceinline__ void cp_commit() { asm volatile("cp.async.commit_group;"); }
template <int N> __device__ __forceinline__ void cp_wait() {
    asm volatile("cp.async.wait_group %0;" :: "n"(N));
}
#define PACK2(d, s) asm("mov.b64 %0, {%1, %1};" : "=l"(d) : "r"(__float_as_uint(s)))
#define FFMA2(acc, a, b) asm("fma.rn.f32x2 %0, %1, %2, %0;" : "+l"(acc) : "l"(a), "l"(b))
#define FADD2(acc, a)    asm("add.rn.f32x2 %0, %0, %1;"     : "+l"(acc) : "l"(a))

__device__ __forceinline__ float2 unpk(ull v) {
    unsigned lo, hi;
    asm("mov.b64 {%0, %1}, %2;" : "=r"(lo), "=r"(hi) : "l"(v));
    float2 f; f.x = __uint_as_float(lo); f.y = __uint_as_float(hi);
    return f;
}

__device__ __forceinline__ void barwait(unsigned* ctr, unsigned target) {
    __syncthreads();
    if (threadIdx.x == 0) {
        asm volatile("red.release.gpu.global.add.u32 [%0], 1;" :: "l"(ctr) : "memory");
        unsigned v;
        do {
            asm volatile("ld.acquire.gpu.global.u32 %0, [%1];" : "=r"(v) : "l"(ctr) : "memory");
        } while (v < target);
    }
    __syncthreads();
}

__global__ void mps_init_kernel(const float* __restrict__ Mg, const float* __restrict__ Hg) {
    int i = blockIdx.x * 256 + threadIdx.x;
    if (i < 160) { g_bars[i] = 0u; if (i < 32) g_fin[i] = 0u; }
    if (i < 655360) {
        int s = i >> 15, r = i & 32767;
        int p = r >> 8, ii = (r >> 7) & 1, a = r & 127;
        g_mT[i] = Mg[(20 + s) * 32768 + a * 256 + ii * 128 + p];
    } else if (i < 660480) {
        int t = i - 655360;
        int s = t >> 8, r = t & 255;
        int x = r >> 5, w = (r >> 2) & 7, ij = r & 3;
        g_hT[t] = Hg[(20 + s) * 256 + w * 32 + x * 4 + ij];
    } else if (i < 791552) {
        int t = i - 660480; g_L[0][t] = (t == 0) ? 1.0f : 0.0f;
    } else if (i < 922624) {
        int t = i - 791552; g_R[0][t] = (t == 896) ? 1.0f : 0.0f;  // [0][W-1][0]
    } else if (i < 939008) {
        int t = i - 922624; g_N[0][t] = (t == 0) ? 1.0f : 0.0f;
    } else if (i < 955392) {
        int t = i - 939008; g_Nr[0][t] = (t == 0) ? 1.0f : 0.0f;
    }
}

__global__ void __launch_bounds__(NTHR, 1)
mps_kernel(const float* __restrict__ Mg, const float* __restrict__ Hg, float* __restrict__ out) {
    extern __shared__ __align__(16) char smem[];
    const int bid = blockIdx.x;
    const int tid = threadIdx.x;
    const int lane = tid & 31, wid = tid >> 5;   // 16 warps
    unsigned nb = 0;
    int cur = 0;

    float* smM   = (float*)(smem + OFF_M);
    float* smT2f = (float*)(smem + OFF_T2F);
    float* smA   = (float*)(smem + OFF_A);
    float* smH   = (float*)(smem + OFF_H);
    float* smT1  = (float*)(smem + OFF_T1S);
    float* smPE0 = (float*)(smem + OFF_PE0);
    float* smPE1 = (float*)(smem + OFF_PE1);
    float* smTn  = (float*)(smem + OFF_TN);
    float* smAn  = (float*)(smem + OFF_AN);
    ull*   smPN  = (ull*)(smem + OFF_PN);

    const bool isE = (bid < 128);
    const int dir = isE ? (bid >> 6) : ((bid - 128) >> 3);
    const int e   = bid & 63;
    const int rn  = (bid - 128) & 7;
    const int w_  = isE ? (e >> 3) : 0;
    const int bch = isE ? ((e >> 1) & 3) : (rn >> 1);
    const int cch = isE ? (e & 1) : (rn & 1);
    const int p0n = (rn >> 1) * 32;
    const int q0n = (rn & 1) * 64;
    float* T1g = dir ? g_T1r : g_T1;
    float* Tng = dir ? g_Tnr : g_Tn;
    ull* smX = (ull*)(smem + (isE ? OFF_X : OFF_XN));
    unsigned* grpCtr = &g_bars[(isE ? dir : (2 + dir)) * 32];
    const unsigned grpSz = isE ? 64u : 8u;

    // prefetch m (+h) for a site; smM and smH must be dead when called
    auto prefetch_mh = [&](int s2) {
        const int site2 = dir ? (NSITE - 1 - s2) : s2;
        const float* mp2 = dir ? (g_mT + (site2 - 20) * 32768) : (Mg + site2 * 32768);
        for (int t = tid; t < 8192; t += NTHR)
            cp16(smM + t * 4, mp2 + t * 4);
        if (isE && tid < 64) {
            const float* hp2 = dir ? (g_hT + (site2 - 20) * 256) : (Hg + site2 * 256);
            cp16(smH + tid * 4, hp2 + tid * 4);
        }
    };

    // prologue: m/h for the first site flow while nothing else is pending
    prefetch_mh(0);
    cp_commit();

    for (int s = 0; s < NSTEP; ++s) {
        const float* envEc = dir ? g_R[cur] : g_L[cur];
        float*       envEn = dir ? g_R[cur ^ 1] : g_L[cur ^ 1];
        const float* envNc = dir ? g_Nr[cur] : g_N[cur];
        float*       envNn = dir ? g_Nr[cur ^ 1] : g_N[cur ^ 1];

        // ---------- env tile load (only barrier-dependent input) ----------
        if (isE) {
            const float* Ab = envEc + w_ * 128 + bch * 32;
            for (int t = tid; t < 1024; t += NTHR)
                cp16(smA + (t >> 3) * 32 + (t & 7) * 4, Ab + (t >> 3) * 1024 + (t & 7) * 4);
        } else {
            const float* Ab = envNc + bch * 32;
            for (int t = tid; t < 1024; t += NTHR)
                cp16(smAn + (t >> 3) * 32 + (t & 7) * 4, Ab + (t >> 3) * 128 + (t & 7) * 4);
        }
        cp_commit();
        cp_wait<0>();            // drains env tile AND the pipelined m/h
        __syncthreads();

        // ---------- Phase A: 32 rows x 128 cols, K=128 ----------
        // warp = (cg: 16-col group, kh: 64-k half); thread = 4 rows x 4 cols
        {
            const float* Ab = isE ? smA : smAn;
            const int cg = wid & 7, kh = wid >> 3;
            const int r4 = lane & 7, c4 = lane >> 3;
            ull acc[8];
#pragma unroll
            for (int u = 0; u < 8; ++u) acc[u] = 0ull;
            const int kbeg = kh * 64;
#pragma unroll 4
            for (int kk = 0; kk < 64; ++kk) {
                const int k = kbeg + kk;
                float4 av = *(const float4*)(Ab + k * 32 + r4 * 4);
                ulonglong2 bv = *(const ulonglong2*)(smM + k * 256 + cch * 128 + cg * 16 + c4 * 4);
                ull a0, a1, a2, a3;
                PACK2(a0, av.x); PACK2(a1, av.y); PACK2(a2, av.z); PACK2(a3, av.w);
                FFMA2(acc[0], a0, bv.x); FFMA2(acc[1], a0, bv.y);
                FFMA2(acc[2], a1, bv.x); FFMA2(acc[3], a1, bv.y);
                FFMA2(acc[4], a2, bv.x); FFMA2(acc[5], a2, bv.y);
                FFMA2(acc[6], a3, bv.x); FFMA2(acc[7], a3, bv.y);
            }
            if (kh == 1) {
#pragma unroll
                for (int u = 0; u < 8; ++u)
                    smX[u * 256 + cg * 32 + lane] = acc[u];
            }
            __syncthreads();
            if (kh == 0) {
#pragma unroll
                for (int u = 0; u < 8; ++u)
                    FADD2(acc[u], smX[u * 256 + cg * 32 + lane]);
                if (isE) {
#pragma unroll
                    for (int rr = 0; rr < 4; ++rr)
#pragma unroll
                        for (int cp = 0; cp < 2; ++cp) {
                            int pp = cg * 8 + c4 * 2 + cp;
                            int b = bch * 32 + r4 * 4 + rr;
                            *(ull*)&T1g[pp * 4096 + (w_ * 2 + cch) * 256 + b * 2] = acc[rr * 2 + cp];
                        }
                } else {
#pragma unroll
                    for (int rr = 0; rr < 4; ++rr)
#pragma unroll
                        for (int cp = 0; cp < 2; ++cp) {
                            int p = cg * 16 + c4 * 4 + cp * 2;
                            int b = bch * 32 + r4 * 4 + rr;
                            *(float2*)&Tng[(b * 2 + cch) * 128 + p] = unpk(acc[rr * 2 + cp]);
                        }
                }
            }
        }
        ++nb; barwait(grpCtr, nb * grpSz);

        // ---------- Phase B ----------
        if (isE) {
            for (int t = tid; t < 1024; t += NTHR)        // T1 block pp = e (4096 floats)
                cp16(smT1 + t * 4, T1g + e * 4096 + t * 4);
            cp_commit();
            cp_wait<0>();
            __syncthreads();
            // T2f[k][20]: pl*8+x plain f32
            {
                const int pl = tid >> 8, kk = tid & 255;
                const int j = kk & 1;
                float t1v[16];
#pragma unroll
                for (int wi = 0; wi < 16; ++wi) t1v[wi] = smT1[wi * 256 + (kk & 254) + pl];
                float a[8];
#pragma unroll
                for (int x = 0; x < 8; ++x) {
                    float v = 0.0f;
#pragma unroll
                    for (int wi = 0; wi < 16; ++wi)
                        v += t1v[wi] * smH[(wi >> 1) * 32 + x * 4 + (wi & 1) * 2 + j];
                    a[x] = v;
                }
                float4 f0; f0.x = a[0]; f0.y = a[1]; f0.z = a[2]; f0.w = a[3];
                float4 f1; f1.x = a[4]; f1.y = a[5]; f1.z = a[6]; f1.w = a[7];
                *(float4*)(smT2f + kk * 20 + pl * 8) = f0;
                *(float4*)(smT2f + kk * 20 + pl * 8 + 4) = f1;
            }
            __syncthreads();
            // main: warp = (pl = wid>>3, kq = wid&7); thread: 8 x * 4 q; 32 k
            const int pl = wid >> 3, kq = wid & 7;
            ull acc[16];
#pragma unroll
            for (int u = 0; u < 16; ++u) acc[u] = 0ull;
#pragma unroll 2
            for (int kk = 0; kk < 32; ++kk) {
                const int k = kq * 32 + kk;
                ulonglong2 mv = *(const ulonglong2*)(smM + k * 128 + lane * 4);
                float4 ta = *(const float4*)(smT2f + k * 20 + pl * 8);
                ull p0v, p1v, p2v, p3v;
                PACK2(p0v, ta.x); PACK2(p1v, ta.y); PACK2(p2v, ta.z); PACK2(p3v, ta.w);
                FFMA2(acc[0], p0v, mv.x); FFMA2(acc[1], p0v, mv.y);
                FFMA2(acc[2], p1v, mv.x); FFMA2(acc[3], p1v, mv.y);
                FFMA2(acc[4], p2v, mv.x); FFMA2(acc[5], p2v, mv.y);
                FFMA2(acc[6], p3v, mv.x); FFMA2(acc[7], p3v, mv.y);
                float4 tb = *(const float4*)(smT2f + k * 20 + pl * 8 + 4);
                PACK2(p0v, tb.x); PACK2(p1v, tb.y); PACK2(p2v, tb.z); PACK2(p3v, tb.w);
                FFMA2(acc[8],  p0v, mv.x); FFMA2(acc[9],  p0v, mv.y);
                FFMA2(acc[10], p1v, mv.x); FFMA2(acc[11], p1v, mv.y);
                FFMA2(acc[12], p2v, mv.x); FFMA2(acc[13], p2v, mv.y);
                FFMA2(acc[14], p3v, mv.x); FFMA2(acc[15], p3v, mv.y);
            }
            __syncthreads();   // all warps done READING smT2f/smM/smH before overwrite
            // pipeline: next site's m/h flow under partials + barrier + env load
            // (m -> 0..128K disjoint from PE1; h -> dead tail @201728, no aliasing)
            if (s + 1 < NSTEP) { prefetch_mh(s + 1); cp_commit(); }
            {
                float* dst = (pl ? smPE1 : smPE0);
#pragma unroll
                for (int x = 0; x < 8; ++x) {
                    ulonglong2 v; v.x = acc[2 * x]; v.y = acc[2 * x + 1];
                    *(ulonglong2*)(dst + (kq * 8 + x) * 128 + lane * 4) = v;
                }
            }
            __syncthreads();
            {
                const int rpl = tid >> 8, x = (tid >> 5) & 7, qg = (tid & 31) * 4;
                const float* src = (rpl ? smPE1 : smPE0);
                ull r0 = 0ull, r1 = 0ull;
#pragma unroll
                for (int kq2 = 0; kq2 < 8; ++kq2) {
                    ulonglong2 v = *(const ulonglong2*)(src + (kq2 * 8 + x) * 128 + qg);
                    FADD2(r0, v.x); FADD2(r1, v.y);
                }
                ulonglong2 w0; w0.x = r0; w0.y = r1;
                *(ulonglong2*)&envEn[(2 * e + rpl) * 1024 + x * 128 + qg] = w0;
            }
        } else {
            for (int t = tid; t < 2048; t += NTHR)        // Tn [256][32 p-slice]
                cp16(smTn + (t >> 3) * 32 + (t & 7) * 4,
                     Tng + (t >> 3) * 128 + p0n + (t & 7) * 4);
            cp_commit();
            cp_wait<0>();
            __syncthreads();
            if (wid < 8) {
                const int qh = wid & 1, kq = wid >> 1;
                const int q = q0n + qh * 32 + lane;
                ull acc[16];
#pragma unroll
                for (int u = 0; u < 16; ++u) acc[u] = 0ull;
#pragma unroll 2
                for (int kk = 0; kk < 64; ++kk) {
                    const int k = kq * 64 + kk;
                    float mq = smM[k * 128 + q];
                    ull mq2; PACK2(mq2, mq);
#pragma unroll
                    for (int c = 0; c < 8; ++c) {
                        ulonglong2 u2 = *(const ulonglong2*)(smTn + k * 32 + c * 4);
                        FFMA2(acc[2 * c], u2.x, mq2);
                        FFMA2(acc[2 * c + 1], u2.y, mq2);
                    }
                }
#pragma unroll
                for (int u = 0; u < 16; ++u)
                    smPN[((kq * 2 + qh) * 16 + u) * 32 + lane] = acc[u];
            }
            __syncthreads();   // smM reads complete
            if (s + 1 < NSTEP) { prefetch_mh(s + 1); cp_commit(); }
            if (tid < 256) {
                const int pp = tid >> 4, qg = (tid & 15) * 4;
                const int qh = qg >> 5, ql = qg & 31;
                ull r[4] = {0ull, 0ull, 0ull, 0ull};
#pragma unroll
                for (int kq = 0; kq < 4; ++kq) {
                    const ull* bp = smPN + ((kq * 2 + qh) * 16 + pp) * 32 + ql;
                    ulonglong2 v0 = *(const ulonglong2*)bp;
                    ulonglong2 v1 = *(const ulonglong2*)(bp + 2);
                    FADD2(r[0], v0.x); FADD2(r[1], v0.y);
                    FADD2(r[2], v1.x); FADD2(r[3], v1.y);
                }
#pragma unroll
                for (int v = 0; v < 4; ++v) {
                    float2 f = unpk(r[v]);
                    int q = q0n + qg + v;
                    envNn[(p0n + 2 * pp) * 128 + q] = f.x;
                    envNn[(p0n + 2 * pp + 1) * 128 + q] = f.y;
                }
            }
        }
        ++nb; barwait(grpCtr, nb * grpSz);
        cur ^= 1;
    }

    // ---------- global join, then dot(L20,R20), dot(Nl20,Nr20) ----------
    barwait(&g_fin[0], NCTA);
    {
        const float *Xp, *Yp; int base;
        if (isE) { Xp = g_L[cur]; Yp = g_R[cur]; base = bid * 1024; }
        else     { Xp = g_N[cur]; Yp = g_Nr[cur]; base = (bid - 128) * 1024; }
        ull dacc = 0ull;
        int t = base + tid * 2;
        ull xa = *(const ull*)(Xp + t);
        ull ya = *(const ull*)(Yp + t);
        FFMA2(dacc, xa, ya);
        float2 df = unpk(dacc);
        float v = df.x + df.y;
#pragma unroll
        for (int off = 16; off > 0; off >>= 1) v += __shfl_xor_sync(~0u, v, off);
        float* smRed = (float*)(smem);
        if (lane == 0) smRed[wid] = v;
        __syncthreads();
        if (tid == 0) {
            float tot = 0.0f;
#pragma unroll
            for (int w2 = 0; w2 < 16; ++w2) tot += smRed[w2];
            g_parts[bid] = tot;
        }
    }
    barwait(&g_fin[0], 2 * NCTA);
    if (bid == 0 && wid == 0) {
        float ev = 0.0f;
#pragma unroll
        for (int r = 0; r < 4; ++r) ev += g_parts[lane + r * 32];
        float nv = (lane < 16) ? g_parts[128 + lane] : 0.0f;
#pragma unroll
        for (int off = 16; off > 0; off >>= 1) {
            ev += __shfl_xor_sync(~0u, ev, off);
            nv += __shfl_xor_sync(~0u, nv, off);
        }
        if (lane == 0) {
            out[0] = ev;
            out[1] = nv;
            out[2] = ev / nv;
            out[3] = fmaxf(nv - 10000.0f, 0.0f);
        }
    }
}

extern "C" void kernel_launch(void* const* d_in, const int* in_sizes, int n_in,
                              void* d_out, int out_size) {
    const float* M = (const float*)d_in[0];
    const float* H = (const float*)d_in[1];
    float* out = (float*)d_out;
    cudaFuncSetAttribute(mps_kernel, cudaFuncAttributeMaxDynamicSharedMemorySize, SMEM_BYTES);
    mps_init_kernel<<<3732, 256>>>(M, H);
    mps_kernel<<<NCTA, NTHR, SMEM_BYTES>>>(M, H, out);
}

// round 17
// speedup vs baseline: 1.0277x; 1.0277x over previous
#include <cuda_runtime.h>

#define NSITE 40
#define NSTEP 20
#define NCTA  144
#define NTHR  512

typedef unsigned long long ull;

__device__ __align__(16) float g_L[2][131072];   // left  env [a][w][b]
__device__ __align__(16) float g_R[2][131072];   // right env [a][x][b]
__device__ __align__(16) float g_N[2][16384];
__device__ __align__(16) float g_Nr[2][16384];
__device__ __align__(16) float g_T1[262144];     // left  T1 [pp][(2w+i)][b*2+pl]
__device__ __align__(16) float g_T1r[262144];    // right T1 same layout
__device__ __align__(16) float g_Tn[32768];      // left  Tn transposed [k][p]
__device__ __align__(16) float g_Tnr[32768];
__device__ __align__(16) float g_mT[655360];     // sites 20..39: [p*256+i*128+a] = m[a,i,p]
__device__ __align__(16) float g_hT[5120];       // sites 20..39: [x*32+w*4+i*2+j]
__device__ float g_parts[NCTA];
__device__ __align__(128) unsigned g_bars[128];  // 4 counters, 128B apart
__device__ __align__(128) unsigned g_fin[32];

// smem (bytes), energy CTA:
//   smM 0(128K)
//   smT2f 131072(20480: [256k][20f] rows, pl*8+x in first 16)
//   smX   151552(16384: phase-A k-split exchange, ull[8][256])
//   smA   167936(16K)
//   smH   201728(1K)  — DEAD TAIL region: never aliased, safe for in-flight prefetch
//   smPE0 @167936(32K = 167936..200704, aliases smA — guarded by syncs)
//   smPE1 @131072(32K, aliases T2f+X — dead after main loop, guarded by sync)
// norm CTA: smM 0(128K) | smTn 131072(32K) | smAn 163840(16K) | smPN 180224(32K)
#define SMEM_BYTES 212992
#define OFF_M    0
#define OFF_T2F  131072
#define OFF_X    151552
#define OFF_A    167936
#define OFF_H    201728
#define OFF_PE0  167936
#define OFF_PE1  131072
#define OFF_TN   131072
#define OFF_AN   163840
#define OFF_PN   180224
#define OFF_XN   180224

__device__ __forceinline__ void cp16(void* s, const void* g) {
    unsigned sa = (unsigned)__cvta_generic_to_shared(s);
    asm volatile("cp.async.cg.shared.global [%0], [%1], 16;" :: "r"(sa), "l"(g));
}
__device__ __forceinline__ void cp_commit() { asm volatile("cp.async.commit_group;"); }
template <int N> __device__ __forceinline__ void cp_wait() {
    asm volatile("cp.async.wait_group %0;" :: "n"(N));
}
#define PACK2(d, s) asm("mov.b64 %0, {%1, %1};" : "=l"(d) : "r"(__float_as_uint(s)))
#define FFMA2(acc, a, b) asm("fma.rn.f32x2 %0, %1, %2, %0;" : "+l"(acc) : "l"(a), "l"(b))
#define FADD2(acc, a)    asm("add.rn.f32x2 %0, %0, %1;"     : "+l"(acc) : "l"(a))

__device__ __forceinline__ float2 unpk(ull v) {
    unsigned lo, hi;
    asm("mov.b64 {%0, %1}, %2;" : "=r"(lo), "=r"(hi) : "l"(v));
    float2 f; f.x = __uint_as_float(lo); f.y = __uint_as_float(hi);
    return f;
}

__device__ __forceinline__ void barwait(unsigned* ctr, unsigned target) {
    __syncthreads();
    if (threadIdx.x == 0) {
        asm volatile("red.release.gpu.global.add.u32 [%0], 1;" :: "l"(ctr) : "memory");
        unsigned v;
        do {
            asm volatile("ld.acquire.gpu.global.u32 %0, [%1];" : "=r"(v) : "l"(ctr) : "memory");
        } while (v < target);
    }
    __syncthreads();
}

// Grid-stride init: 296 blocks x 512 thr = 2 waves (was 3732 blocks = 26 waves)
__global__ void mps_init_kernel(const float* __restrict__ Mg, const float* __restrict__ Hg) {
    for (int i = blockIdx.x * 512 + threadIdx.x; i < 955392; i += 296 * 512) {
        if (i < 160) { g_bars[i] = 0u; if (i < 32) g_fin[i] = 0u; }
        if (i < 655360) {
            int s = i >> 15, r = i & 32767;
            int p = r >> 8, ii = (r >> 7) & 1, a = r & 127;
            g_mT[i] = Mg[(20 + s) * 32768 + a * 256 + ii * 128 + p];
        } else if (i < 660480) {
            int t = i - 655360;
            int s = t >> 8, r = t & 255;
            int x = r >> 5, w = (r >> 2) & 7, ij = r & 3;
            g_hT[t] = Hg[(20 + s) * 256 + w * 32 + x * 4 + ij];
        } else if (i < 791552) {
            int t = i - 660480; g_L[0][t] = (t == 0) ? 1.0f : 0.0f;
        } else if (i < 922624) {
            int t = i - 791552; g_R[0][t] = (t == 896) ? 1.0f : 0.0f;  // [0][W-1][0]
        } else if (i < 939008) {
            int t = i - 922624; g_N[0][t] = (t == 0) ? 1.0f : 0.0f;
        } else {
            int t = i - 939008; g_Nr[0][t] = (t == 0) ? 1.0f : 0.0f;
        }
    }
}

__global__ void __launch_bounds__(NTHR, 1)
mps_kernel(const float* __restrict__ Mg, const float* __restrict__ Hg, float* __restrict__ out) {
    extern __shared__ __align__(16) char smem[];
    const int bid = blockIdx.x;
    const int tid = threadIdx.x;
    const int lane = tid & 31, wid = tid >> 5;   // 16 warps
    unsigned nb = 0;
    int cur = 0;

    float* smM   = (float*)(smem + OFF_M);
    float* smT2f = (float*)(smem + OFF_T2F);
    float* smA   = (float*)(smem + OFF_A);
    float* smH   = (float*)(smem + OFF_H);
    float* smPE0 = (float*)(smem + OFF_PE0);
    float* smPE1 = (float*)(smem + OFF_PE1);
    float* smTn  = (float*)(smem + OFF_TN);
    float* smAn  = (float*)(smem + OFF_AN);
    ull*   smPN  = (ull*)(smem + OFF_PN);

    const bool isE = (bid < 128);
    const int dir = isE ? (bid >> 6) : ((bid - 128) >> 3);
    const int e   = bid & 63;
    const int rn  = (bid - 128) & 7;
    const int w_  = isE ? (e >> 3) : 0;
    const int bch = isE ? ((e >> 1) & 3) : (rn >> 1);
    const int cch = isE ? (e & 1) : (rn & 1);
    const int p0n = (rn >> 1) * 32;
    const int q0n = (rn & 1) * 64;
    float* T1g = dir ? g_T1r : g_T1;
    float* Tng = dir ? g_Tnr : g_Tn;
    ull* smX = (ull*)(smem + (isE ? OFF_X : OFF_XN));
    unsigned* grpCtr = &g_bars[(isE ? dir : (2 + dir)) * 32];
    const unsigned grpSz = isE ? 64u : 8u;

    // prefetch m (+h) for a site; smM and smH must be dead when called
    auto prefetch_mh = [&](int s2) {
        const int site2 = dir ? (NSITE - 1 - s2) : s2;
        const float* mp2 = dir ? (g_mT + (site2 - 20) * 32768) : (Mg + site2 * 32768);
        for (int t = tid; t < 8192; t += NTHR)
            cp16(smM + t * 4, mp2 + t * 4);
        if (isE && tid < 64) {
            const float* hp2 = dir ? (g_hT + (site2 - 20) * 256) : (Hg + site2 * 256);
            cp16(smH + tid * 4, hp2 + tid * 4);
        }
    };

    // prologue: m/h for the first site flow while nothing else is pending
    prefetch_mh(0);
    cp_commit();

    for (int s = 0; s < NSTEP; ++s) {
        const float* envEc = dir ? g_R[cur] : g_L[cur];
        float*       envEn = dir ? g_R[cur ^ 1] : g_L[cur ^ 1];
        const float* envNc = dir ? g_Nr[cur] : g_N[cur];
        float*       envNn = dir ? g_Nr[cur ^ 1] : g_N[cur ^ 1];

        // ---------- env tile load (only barrier-dependent input) ----------
        if (isE) {
            const float* Ab = envEc + w_ * 128 + bch * 32;
            for (int t = tid; t < 1024; t += NTHR)
                cp16(smA + (t >> 3) * 32 + (t & 7) * 4, Ab + (t >> 3) * 1024 + (t & 7) * 4);
        } else {
            const float* Ab = envNc + bch * 32;
            for (int t = tid; t < 1024; t += NTHR)
                cp16(smAn + (t >> 3) * 32 + (t & 7) * 4, Ab + (t >> 3) * 128 + (t & 7) * 4);
        }
        cp_commit();
        cp_wait<0>();            // drains env tile AND the pipelined m/h
        __syncthreads();

        // ---------- Phase A: 32 rows x 128 cols, K=128 ----------
        // warp = (cg: 16-col group, kh: 64-k half); thread = 4 rows x 4 cols
        {
            const float* Ab = isE ? smA : smAn;
            const int cg = wid & 7, kh = wid >> 3;
            const int r4 = lane & 7, c4 = lane >> 3;
            ull acc[8];
#pragma unroll
            for (int u = 0; u < 8; ++u) acc[u] = 0ull;
            const int kbeg = kh * 64;
#pragma unroll 4
            for (int kk = 0; kk < 64; ++kk) {
                const int k = kbeg + kk;
                float4 av = *(const float4*)(Ab + k * 32 + r4 * 4);
                ulonglong2 bv = *(const ulonglong2*)(smM + k * 256 + cch * 128 + cg * 16 + c4 * 4);
                ull a0, a1, a2, a3;
                PACK2(a0, av.x); PACK2(a1, av.y); PACK2(a2, av.z); PACK2(a3, av.w);
                FFMA2(acc[0], a0, bv.x); FFMA2(acc[1], a0, bv.y);
                FFMA2(acc[2], a1, bv.x); FFMA2(acc[3], a1, bv.y);
                FFMA2(acc[4], a2, bv.x); FFMA2(acc[5], a2, bv.y);
                FFMA2(acc[6], a3, bv.x); FFMA2(acc[7], a3, bv.y);
            }
            if (kh == 1) {
#pragma unroll
                for (int u = 0; u < 8; ++u)
                    smX[u * 256 + cg * 32 + lane] = acc[u];
            }
            __syncthreads();
            if (kh == 0) {
#pragma unroll
                for (int u = 0; u < 8; ++u)
                    FADD2(acc[u], smX[u * 256 + cg * 32 + lane]);
                if (isE) {
#pragma unroll
                    for (int rr = 0; rr < 4; ++rr)
#pragma unroll
                        for (int cp = 0; cp < 2; ++cp) {
                            int pp = cg * 8 + c4 * 2 + cp;
                            int b = bch * 32 + r4 * 4 + rr;
                            *(ull*)&T1g[pp * 4096 + (w_ * 2 + cch) * 256 + b * 2] = acc[rr * 2 + cp];
                        }
                } else {
#pragma unroll
                    for (int rr = 0; rr < 4; ++rr)
#pragma unroll
                        for (int cp = 0; cp < 2; ++cp) {
                            int p = cg * 16 + c4 * 4 + cp * 2;
                            int b = bch * 32 + r4 * 4 + rr;
                            *(float2*)&Tng[(b * 2 + cch) * 128 + p] = unpk(acc[rr * 2 + cp]);
                        }
                }
            }
        }
        ++nb; barwait(grpCtr, nb * grpSz);

        // ---------- Phase B ----------
        if (isE) {
            // T2f[k][20]: pl*8+x plain f32; T1 read DIRECTLY from global (L2-hit,
            // MLP=16 independent loads/thread, hidden across 16 warps) — no cp round trip
            {
                const int pl = tid >> 8, kk = tid & 255;
                const int j = kk & 1;
                const float* t1gp = T1g + e * 4096 + (kk & 254) + pl;
                float t1v[16];
#pragma unroll
                for (int wi = 0; wi < 16; ++wi) t1v[wi] = t1gp[wi * 256];
                float a[8];
#pragma unroll
                for (int x = 0; x < 8; ++x) {
                    float v = 0.0f;
#pragma unroll
                    for (int wi = 0; wi < 16; ++wi)
                        v += t1v[wi] * smH[(wi >> 1) * 32 + x * 4 + (wi & 1) * 2 + j];
                    a[x] = v;
                }
                float4 f0; f0.x = a[0]; f0.y = a[1]; f0.z = a[2]; f0.w = a[3];
                float4 f1; f1.x = a[4]; f1.y = a[5]; f1.z = a[6]; f1.w = a[7];
                *(float4*)(smT2f + kk * 20 + pl * 8) = f0;
                *(float4*)(smT2f + kk * 20 + pl * 8 + 4) = f1;
            }
            __syncthreads();
            // main: warp = (pl = wid>>3, kq = wid&7); thread: 8 x * 4 q; 32 k
            const int pl = wid >> 3, kq = wid & 7;
            ull acc[16];
#pragma unroll
            for (int u = 0; u < 16; ++u) acc[u] = 0ull;
#pragma unroll 2
            for (int kk = 0; kk < 32; ++kk) {
                const int k = kq * 32 + kk;
                ulonglong2 mv = *(const ulonglong2*)(smM + k * 128 + lane * 4);
                float4 ta = *(const float4*)(smT2f + k * 20 + pl * 8);
                ull p0v, p1v, p2v, p3v;
                PACK2(p0v, ta.x); PACK2(p1v, ta.y); PACK2(p2v, ta.z); PACK2(p3v, ta.w);
                FFMA2(acc[0], p0v, mv.x); FFMA2(acc[1], p0v, mv.y);
                FFMA2(acc[2], p1v, mv.x); FFMA2(acc[3], p1v, mv.y);
                FFMA2(acc[4], p2v, mv.x); FFMA2(acc[5], p2v, mv.y);
                FFMA2(acc[6], p3v, mv.x); FFMA2(acc[7], p3v, mv.y);
                float4 tb = *(const float4*)(smT2f + k * 20 + pl * 8 + 4);
                PACK2(p0v, tb.x); PACK2(p1v, tb.y); PACK2(p2v, tb.z); PACK2(p3v, tb.w);
                FFMA2(acc[8],  p0v, mv.x); FFMA2(acc[9],  p0v, mv.y);
                FFMA2(acc[10], p1v, mv.x); FFMA2(acc[11], p1v, mv.y);
                FFMA2(acc[12], p2v, mv.x); FFMA2(acc[13], p2v, mv.y);
                FFMA2(acc[14], p3v, mv.x); FFMA2(acc[15], p3v, mv.y);
            }
            __syncthreads();   // all warps done READING smT2f/smM/smH before overwrite
            // pipeline: next site's m/h flow under partials + barrier + env load
            if (s + 1 < NSTEP) { prefetch_mh(s + 1); cp_commit(); }
            {
                float* dst = (pl ? smPE1 : smPE0);
#pragma unroll
                for (int x = 0; x < 8; ++x) {
                    ulonglong2 v; v.x = acc[2 * x]; v.y = acc[2 * x + 1];
                    *(ulonglong2*)(dst + (kq * 8 + x) * 128 + lane * 4) = v;
                }
            }
            __syncthreads();
            {
                const int rpl = tid >> 8, x = (tid >> 5) & 7, qg = (tid & 31) * 4;
                const float* src = (rpl ? smPE1 : smPE0);
                ull r0 = 0ull, r1 = 0ull;
#pragma unroll
                for (int kq2 = 0; kq2 < 8; ++kq2) {
                    ulonglong2 v = *(const ulonglong2*)(src + (kq2 * 8 + x) * 128 + qg);
                    FADD2(r0, v.x); FADD2(r1, v.y);
                }
                ulonglong2 w0; w0.x = r0; w0.y = r1;
                *(ulonglong2*)&envEn[(2 * e + rpl) * 1024 + x * 128 + qg] = w0;
            }
        } else {
            for (int t = tid; t < 2048; t += NTHR)        // Tn [256][32 p-slice]
                cp16(smTn + (t >> 3) * 32 + (t & 7) * 4,
                     Tng + (t >> 3) * 128 + p0n + (t & 7) * 4);
            cp_commit();
            cp_wait<0>();
            __syncthreads();
            if (wid < 8) {
                const int qh = wid & 1, kq = wid >> 1;
                const int q = q0n + qh * 32 + lane;
                ull acc[16];
#pragma unroll
                for (int u = 0; u < 16; ++u) acc[u] = 0ull;
#pragma unroll 2
                for (int kk = 0; kk < 64; ++kk) {
                    const int k = kq * 64 + kk;
                    float mq = smM[k * 128 + q];
                    ull mq2; PACK2(mq2, mq);
#pragma unroll
                    for (int c = 0; c < 8; ++c) {
                        ulonglong2 u2 = *(const ulonglong2*)(smTn + k * 32 + c * 4);
                        FFMA2(acc[2 * c], u2.x, mq2);
                        FFMA2(acc[2 * c + 1], u2.y, mq2);
                    }
                }
#pragma unroll
                for (int u = 0; u < 16; ++u)
                    smPN[((kq * 2 + qh) * 16 + u) * 32 + lane] = acc[u];
            }
            __syncthreads();   // smM reads complete
            if (s + 1 < NSTEP) { prefetch_mh(s + 1); cp_commit(); }
            if (tid < 256) {
                const int pp = tid >> 4, qg = (tid & 15) * 4;
                const int qh = qg >> 5, ql = qg & 31;
                ull r[4] = {0ull, 0ull, 0ull, 0ull};
#pragma unroll
                for (int kq = 0; kq < 4; ++kq) {
                    const ull* bp = smPN + ((kq * 2 + qh) * 16 + pp) * 32 + ql;
                    ulonglong2 v0 = *(const ulonglong2*)bp;
                    ulonglong2 v1 = *(const ulonglong2*)(bp + 2);
                    FADD2(r[0], v0.x); FADD2(r[1], v0.y);
                    FADD2(r[2], v1.x); FADD2(r[3], v1.y);
                }
#pragma unroll
                for (int v = 0; v < 4; ++v) {
                    float2 f = unpk(r[v]);
                    int q = q0n + qg + v;
                    envNn[(p0n + 2 * pp) * 128 + q] = f.x;
                    envNn[(p0n + 2 * pp + 1) * 128 + q] = f.y;
                }
            }
        }
        ++nb; barwait(grpCtr, nb * grpSz);
        cur ^= 1;
    }

    // ---------- global join, then dot(L20,R20), dot(Nl20,Nr20) ----------
    barwait(&g_fin[0], NCTA);
    {
        const float *Xp, *Yp; int base;
        if (isE) { Xp = g_L[cur]; Yp = g_R[cur]; base = bid * 1024; }
        else     { Xp = g_N[cur]; Yp = g_Nr[cur]; base = (bid - 128) * 1024; }
        ull dacc = 0ull;
        int t = base + tid * 2;
        ull xa = *(const ull*)(Xp + t);
        ull ya = *(const ull*)(Yp + t);
        FFMA2(dacc, xa, ya);
        float2 df = unpk(dacc);
        float v = df.x + df.y;
#pragma unroll
        for (int off = 16; off > 0; off >>= 1) v += __shfl_xor_sync(~0u, v, off);
        float* smRed = (float*)(smem);
        if (lane == 0) smRed[wid] = v;
        __syncthreads();
        if (tid == 0) {
            float tot = 0.0f;
#pragma unroll
            for (int w2 = 0; w2 < 16; ++w2) tot += smRed[w2];
            g_parts[bid] = tot;
        }
    }
    barwait(&g_fin[0], 2 * NCTA);
    if (bid == 0 && wid == 0) {
        float ev = 0.0f;
#pragma unroll
        for (int r = 0; r < 4; ++r) ev += g_parts[lane + r * 32];
        float nv = (lane < 16) ? g_parts[128 + lane] : 0.0f;
#pragma unroll
        for (int off = 16; off > 0; off >>= 1) {
            ev += __shfl_xor_sync(~0u, ev, off);
            nv += __shfl_xor_sync(~0u, nv, off);
        }
        if (lane == 0) {
            out[0] = ev;
            out[1] = nv;
            out[2] = ev / nv;
            out[3] = fmaxf(nv - 10000.0f, 0.0f);
        }
    }
}

extern "C" void kernel_launch(void* const* d_in, const int* in_sizes, int n_in,
                              void* d_out, int out_size) {
    const float* M = (const float*)d_in[0];
    const float* H = (const float*)d_in[1];
    float* out = (float*)d_out;
    cudaFuncSetAttribute(mps_kernel, cudaFuncAttributeMaxDynamicSharedMemorySize, SMEM_BYTES);
    mps_init_kernel<<<296, 512>>>(M, H);
    mps_kernel<<<NCTA, NTHR, SMEM_BYTES>>>(M, H, out);
}